// round 11
// baseline (speedup 1.0000x reference)
#include <cuda_runtime.h>
#include <cuda_bf16.h>

// MaxBlurPooling1D: x (16, 8192, 256) f32 -> z (16, 4096, 256) f32
// z[b,j,c] = w0*m[2j-1] + w1*m[2j] + w2*m[2j+1] + w3*m[2j+2]
//   m[l] = max(x[l], x[l+1]) for l<=L-2 ; m[L-1] = x[L-1] ; m[-1] = m[L] = 0
//
// Round-10: all 16B-per-lane variants plateau at 5.6-5.9 TB/s regardless of
// batching depth -> LSU request slots are the cap. Double BYTES PER REQUEST:
// 256-bit loads (ld.global.nc.v8.f32, sm_100+), 32 lanes x 32B per row.
// Body structure = R4 (rolling window, per-iteration guard, full unroll) —
// the schedule that measured best (30.5us, 73.7% DRAM).

#define L_DIM  8192
#define CF     256     // f32 channels per row
#define J_OUT  4096
#define JPT    16      // outputs per thread along L
#define BY     4       // warps per block (32 lanes each)

struct f8 { float4 a, b; };

__device__ __forceinline__ f8 ldg256(const float* p) {
    f8 v;
    asm volatile("ld.global.nc.v8.f32 {%0,%1,%2,%3,%4,%5,%6,%7}, [%8];"
                 : "=f"(v.a.x), "=f"(v.a.y), "=f"(v.a.z), "=f"(v.a.w),
                   "=f"(v.b.x), "=f"(v.b.y), "=f"(v.b.z), "=f"(v.b.w)
                 : "l"(p));
    return v;
}

__device__ __forceinline__ float4 f4max(float4 a, float4 b) {
    return make_float4(fmaxf(a.x, b.x), fmaxf(a.y, b.y),
                       fmaxf(a.z, b.z), fmaxf(a.w, b.w));
}

__device__ __forceinline__ f8 f8max(f8 x, f8 y) {
    f8 r; r.a = f4max(x.a, y.a); r.b = f4max(x.b, y.b); return r;
}

__device__ __forceinline__ float4 f4blend(float4 a, float4 b, float4 c, float4 d,
                                          float w0, float w1, float w2, float w3) {
    float4 o;
    o.x = w0 * a.x + w1 * b.x + w2 * c.x + w3 * d.x;
    o.y = w0 * a.y + w1 * b.y + w2 * c.y + w3 * d.y;
    o.z = w0 * a.z + w1 * b.z + w2 * c.z + w3 * d.z;
    o.w = w0 * a.w + w1 * b.w + w2 * c.w + w3 * d.w;
    return o;
}

__device__ __forceinline__ void st8(float* p, f8 v) {
    asm volatile("st.global.v4.f32 [%0], {%1,%2,%3,%4};"
                 :: "l"(p), "f"(v.a.x), "f"(v.a.y), "f"(v.a.z), "f"(v.a.w));
    asm volatile("st.global.v4.f32 [%0], {%1,%2,%3,%4};"
                 :: "l"(p + 4), "f"(v.b.x), "f"(v.b.y), "f"(v.b.z), "f"(v.b.w));
}

__global__ void __launch_bounds__(128)
mbp1d_kernel(const float* __restrict__ x,
             const float* __restrict__ blur,
             const float* __restrict__ avg,
             float*       __restrict__ z)
{
    // Fold blur (b0,b1,b2) and avg (a0,a1) into 4 taps over m[]
    const float b0 = blur[0], b1 = blur[1], b2 = blur[2];
    const float a0 = avg[0],  a1 = avg[1];
    const float w0 = a0 * b0;
    const float w1 = a0 * b1 + a1 * b0;
    const float w2 = a0 * b2 + a1 * b1;
    const float w3 = a1 * b2;

    const int lane = threadIdx.x;                                 // 0..31, 8 floats each
    const int b    = blockIdx.y;                                  // batch
    const int j0   = (blockIdx.x * BY + threadIdx.y) * JPT;       // first output row

    const float* xb = x + (size_t)b * L_DIM * CF + lane * 8;
    float*       zb = z + ((size_t)b * J_OUT + j0) * CF + lane * 8;

    f8 zero; zero.a = make_float4(0.f, 0.f, 0.f, 0.f); zero.b = zero.a;

    // Rolling state at loop top for iteration j:
    //   mA = m[2j-1], mB = m[2j], xlast = x[2j+1]
    f8 mA, mB, xlast;
    {
        const f8 x0 = ldg256(xb + (size_t)(2 * j0) * CF);
        const f8 x1 = ldg256(xb + (size_t)(2 * j0 + 1) * CF);
        if (j0 == 0) {
            mA = zero;                                            // m[-1] = 0 (pad)
        } else {
            const f8 xm1 = ldg256(xb + (size_t)(2 * j0 - 1) * CF);
            mA = f8max(xm1, x0);
        }
        mB = f8max(x0, x1);
        xlast = x1;
    }

    #pragma unroll
    for (int t = 0; t < JPT; ++t) {
        const int j  = j0 + t;
        const int r2 = 2 * j + 2;                                 // next even row
        f8 mC, mD;
        if (r2 < L_DIM) {
            const f8 x2 = ldg256(xb + (size_t)r2 * CF);
            const f8 x3 = ldg256(xb + (size_t)(r2 + 1) * CF);     // r2 even => r2+1 <= 8191
            mC = f8max(xlast, x2);                                // m[2j+1]
            mD = f8max(x2, x3);                                   // m[2j+2]
            xlast = x3;
        } else {
            // j = 4095: m[8191] = x[8191] (pad is NEG_INF), m[8192] = 0 (zero pad)
            mC = xlast;
            mD = zero;
        }

        f8 o;
        o.a = f4blend(mA.a, mB.a, mC.a, mD.a, w0, w1, w2, w3);
        o.b = f4blend(mA.b, mB.b, mC.b, mD.b, w0, w1, w2, w3);
        st8(zb + (size_t)t * CF, o);

        mA = mC;
        mB = mD;
    }
}

extern "C" void kernel_launch(void* const* d_in, const int* in_sizes, int n_in,
                              void* d_out, int out_size)
{
    const float* x    = (const float*)d_in[0];     // (16, 8192, 256) f32
    const float* blur = (const float*)d_in[1];     // (3,1,1)
    const float* avg  = (const float*)d_in[2];     // (2,1,1)
    float*       z    = (float*)d_out;             // (16, 4096, 256) f32

    (void)in_sizes; (void)n_in; (void)out_size;

    dim3 block(32, BY);                            // (32, 4) = 128 threads
    dim3 grid(J_OUT / (BY * JPT), 16);             // (64, 16) = 1024 blocks
    mbp1d_kernel<<<grid, block>>>(x, blur, avg, z);
}